// round 1
// baseline (speedup 1.0000x reference)
#include <cuda_runtime.h>
#include <cstdint>

// Problem constants
#define BSZ   8
#define CDIM  384
#define NTOK  1024
#define NH    12
#define DH    32
#define O3    1152   // 3*CDIM
static constexpr float SCALE = 0.17677669529663687f;  // 32^-0.5

// Scratch (device globals; no allocations allowed)
static __device__ float g_q[(size_t)BSZ * NH * NTOK * DH];
static __device__ float g_k[(size_t)BSZ * NH * NTOK * DH];
static __device__ float g_v[(size_t)BSZ * NH * NTOK * DH];
static __device__ float g_o[(size_t)BSZ * NTOK * CDIM];

// ---------------------------------------------------------------------------
// Kernel 1: QKV projection.
// out[b, m, o] = sum_c x[b, c, m] * Wqkv[o, c],  o = s*384 + h*32 + d
// Routed directly into g_q/g_k/g_v with layout [B][h][N][d].
// 128x128 tile, BK=16, 256 threads, 8x8 register tile (split 4+4).
// ---------------------------------------------------------------------------
__global__ __launch_bounds__(256) void qkv_gemm(const float* __restrict__ x,
                                                const float* __restrict__ W) {
    int b  = blockIdx.z;
    int m0 = blockIdx.x * 128;   // token tile
    int o0 = blockIdx.y * 128;   // output-feature tile (0..1151)
    __shared__ float As[16][128];
    __shared__ float Bs[16][128];
    int t  = threadIdx.x;
    int tx = t & 15, ty = t >> 4;

    float acc[8][8];
#pragma unroll
    for (int i = 0; i < 8; i++)
#pragma unroll
        for (int j = 0; j < 8; j++) acc[i][j] = 0.f;

    const float* xb = x + (size_t)b * CDIM * NTOK;

    for (int k0 = 0; k0 < CDIM; k0 += 16) {
        // Load A tile: As[kk][mm] = x[b][k0+kk][m0+mm] (contiguous in m)
        {
            int kk = t >> 5;          // 0..7
            int m4 = (t & 31) * 4;    // 0..124
            const float* src = xb + (size_t)(k0 + kk) * NTOK + m0 + m4;
            *(float4*)&As[kk][m4]     = *(const float4*)src;
            *(float4*)&As[kk + 8][m4] = *(const float4*)(src + 8 * NTOK);
        }
        // Load B tile: Bs[kk][oo] = W[(o0+oo)*384 + k0+kk] (contiguous in k)
        {
            int oo = t >> 1;          // 0..127
            int k8 = (t & 1) * 8;     // 0 or 8
            const float* ws = W + (size_t)(o0 + oo) * CDIM + k0 + k8;
            float4 w0 = *(const float4*)ws;
            float4 w1 = *(const float4*)(ws + 4);
            Bs[k8 + 0][oo] = w0.x; Bs[k8 + 1][oo] = w0.y;
            Bs[k8 + 2][oo] = w0.z; Bs[k8 + 3][oo] = w0.w;
            Bs[k8 + 4][oo] = w1.x; Bs[k8 + 5][oo] = w1.y;
            Bs[k8 + 6][oo] = w1.z; Bs[k8 + 7][oo] = w1.w;
        }
        __syncthreads();
#pragma unroll
        for (int kk = 0; kk < 16; kk++) {
            float4 a0 = *(float4*)&As[kk][ty * 4];
            float4 a1 = *(float4*)&As[kk][64 + ty * 4];
            float4 b0 = *(float4*)&Bs[kk][tx * 4];
            float4 b1 = *(float4*)&Bs[kk][64 + tx * 4];
            float am[8] = {a0.x, a0.y, a0.z, a0.w, a1.x, a1.y, a1.z, a1.w};
            float bn[8] = {b0.x, b0.y, b0.z, b0.w, b1.x, b1.y, b1.z, b1.w};
#pragma unroll
            for (int i = 0; i < 8; i++)
#pragma unroll
                for (int j = 0; j < 8; j++) acc[i][j] += am[i] * bn[j];
        }
        __syncthreads();
    }

    // Epilogue: route o -> (s, h, d). 4 consecutive o never cross a 32-boundary.
#pragma unroll
    for (int gi = 0; gi < 2; gi++)
#pragma unroll
        for (int i = 0; i < 4; i++) {
            int m = m0 + gi * 64 + ty * 4 + i;
#pragma unroll
            for (int gj = 0; gj < 2; gj++) {
                int o   = o0 + gj * 64 + tx * 4;
                int s   = o / CDIM;
                int rem = o - s * CDIM;
                int h   = rem >> 5;
                int d   = rem & 31;
                float* dst = (s == 0) ? g_q : (s == 1) ? g_k : g_v;
                size_t idx = (((size_t)b * NH + h) * NTOK + m) * DH + d;
                float4 v4 = make_float4(acc[gi * 4 + i][gj * 4 + 0],
                                        acc[gi * 4 + i][gj * 4 + 1],
                                        acc[gi * 4 + i][gj * 4 + 2],
                                        acc[gi * 4 + i][gj * 4 + 3]);
                *(float4*)&dst[idx] = v4;
            }
        }
}

// ---------------------------------------------------------------------------
// Kernel 2: flash attention (online softmax), warp-per-query.
// Block = 256 threads = 8 warps = 8 queries. K/V chunks of 128 rows in smem
// (stride 36 floats -> conflict-free LDS.128). q in registers, SCALE folded.
// ---------------------------------------------------------------------------
__global__ __launch_bounds__(256) void flash_attn() {
    __shared__ float smem[2 * 128 * 36];   // Ks | Vs ; reused for reduction
    float* Ks = smem;
    float* Vs = smem + 128 * 36;

    int b    = blockIdx.z;
    int h    = blockIdx.y;
    int w    = threadIdx.x >> 5;
    int lane = threadIdx.x & 31;
    int qidx = blockIdx.x * 8 + w;

    size_t base = ((size_t)(b * NH + h) * NTOK) * DH;
    const float4* qptr = (const float4*)(g_q + base + (size_t)qidx * DH);

    float4 q[8];
#pragma unroll
    for (int i = 0; i < 8; i++) {
        q[i] = qptr[i];
        q[i].x *= SCALE; q[i].y *= SCALE; q[i].z *= SCALE; q[i].w *= SCALE;
    }

    float mr = -1e30f, lr = 0.f;
    float acc[32];
#pragma unroll
    for (int d = 0; d < 32; d++) acc[d] = 0.f;

    for (int c = 0; c < 8; c++) {
        __syncthreads();   // protect previous chunk's smem from overwrite
        const float4* kc = (const float4*)(g_k + base + (size_t)c * 128 * DH);
        const float4* vc = (const float4*)(g_v + base + (size_t)c * 128 * DH);
#pragma unroll
        for (int i = 0; i < 4; i++) {
            int f4 = threadIdx.x + i * 256;        // 0..1023
            int r  = f4 >> 3, d4 = f4 & 7;
            *(float4*)&Ks[r * 36 + d4 * 4] = kc[f4];
            *(float4*)&Vs[r * 36 + d4 * 4] = vc[f4];
        }
        __syncthreads();

        // scores for this warp's query against 4 keys per lane
        float p[4];
        float mc = -1e30f;
#pragma unroll
        for (int ki = 0; ki < 4; ki++) {
            int j = lane + ki * 32;
            float s = 0.f;
#pragma unroll
            for (int d4 = 0; d4 < 8; d4++) {
                float4 kv = *(float4*)&Ks[j * 36 + d4 * 4];
                s += q[d4].x * kv.x + q[d4].y * kv.y +
                     q[d4].z * kv.z + q[d4].w * kv.w;
            }
            p[ki] = s;
            mc = fmaxf(mc, s);
        }
#pragma unroll
        for (int off = 16; off; off >>= 1)
            mc = fmaxf(mc, __shfl_xor_sync(0xffffffffu, mc, off));

        float mn    = fmaxf(mr, mc);
        float alpha = __expf(mr - mn);
        lr *= alpha;
#pragma unroll
        for (int d = 0; d < 32; d++) acc[d] *= alpha;

#pragma unroll
        for (int ki = 0; ki < 4; ki++) {
            float pk = __expf(p[ki] - mn);
            lr += pk;
            int j = lane + ki * 32;
#pragma unroll
            for (int d4 = 0; d4 < 8; d4++) {
                float4 vv = *(float4*)&Vs[j * 36 + d4 * 4];
                acc[d4 * 4 + 0] += pk * vv.x;
                acc[d4 * 4 + 1] += pk * vv.y;
                acc[d4 * 4 + 2] += pk * vv.z;
                acc[d4 * 4 + 3] += pk * vv.w;
            }
        }
        mr = mn;
    }

    // Cross-lane reduction of the distributed accumulator via smem (reused).
    __syncthreads();
    float* red = smem + w * (32 * 33);     // 8*1056 = 8448 <= 9216 floats
#pragma unroll
    for (int d = 0; d < 32; d++) red[lane * 33 + d] = acc[d];
    __syncwarp();
    float s = 0.f;
#pragma unroll
    for (int j = 0; j < 32; j++) s += red[j * 33 + lane];
#pragma unroll
    for (int off = 16; off; off >>= 1)
        lr += __shfl_xor_sync(0xffffffffu, lr, off);

    g_o[((size_t)b * NTOK + qidx) * CDIM + h * DH + lane] = s / lr;
}

// ---------------------------------------------------------------------------
// Kernel 3: output projection + bias, transposed store.
// out[b, o, m] = sum_k g_o[b, m, k] * Wp[o, k] + bias[o]
// tx <-> token m for coalesced float4 stores along m.
// ---------------------------------------------------------------------------
__global__ __launch_bounds__(256) void proj_gemm(const float* __restrict__ W,
                                                 const float* __restrict__ bias,
                                                 float* __restrict__ out) {
    int b  = blockIdx.z;
    int m0 = blockIdx.x * 128;   // token tile
    int o0 = blockIdx.y * 128;   // output-channel tile (0..383)
    __shared__ float As[16][128];
    __shared__ float Bs[16][128];
    int t  = threadIdx.x;
    int tx = t & 15, ty = t >> 4;

    float acc[8][8];   // [m][o]
#pragma unroll
    for (int i = 0; i < 8; i++)
#pragma unroll
        for (int j = 0; j < 8; j++) acc[i][j] = 0.f;

    const float* ao = g_o + (size_t)b * NTOK * CDIM;

    for (int k0 = 0; k0 < CDIM; k0 += 16) {
        {
            int mm = t >> 1;
            int k8 = (t & 1) * 8;
            const float* src = ao + (size_t)(m0 + mm) * CDIM + k0 + k8;
            float4 a0 = *(const float4*)src;
            float4 a1 = *(const float4*)(src + 4);
            As[k8 + 0][mm] = a0.x; As[k8 + 1][mm] = a0.y;
            As[k8 + 2][mm] = a0.z; As[k8 + 3][mm] = a0.w;
            As[k8 + 4][mm] = a1.x; As[k8 + 5][mm] = a1.y;
            As[k8 + 6][mm] = a1.z; As[k8 + 7][mm] = a1.w;

            const float* ws = W + (size_t)(o0 + mm) * CDIM + k0 + k8;
            float4 w0 = *(const float4*)ws;
            float4 w1 = *(const float4*)(ws + 4);
            Bs[k8 + 0][mm] = w0.x; Bs[k8 + 1][mm] = w0.y;
            Bs[k8 + 2][mm] = w0.z; Bs[k8 + 3][mm] = w0.w;
            Bs[k8 + 4][mm] = w1.x; Bs[k8 + 5][mm] = w1.y;
            Bs[k8 + 6][mm] = w1.z; Bs[k8 + 7][mm] = w1.w;
        }
        __syncthreads();
#pragma unroll
        for (int kk = 0; kk < 16; kk++) {
            float4 a0 = *(float4*)&As[kk][tx * 4];
            float4 a1 = *(float4*)&As[kk][64 + tx * 4];
            float4 b0 = *(float4*)&Bs[kk][ty * 4];
            float4 b1 = *(float4*)&Bs[kk][64 + ty * 4];
            float am[8] = {a0.x, a0.y, a0.z, a0.w, a1.x, a1.y, a1.z, a1.w};
            float bn[8] = {b0.x, b0.y, b0.z, b0.w, b1.x, b1.y, b1.z, b1.w};
#pragma unroll
            for (int i = 0; i < 8; i++)
#pragma unroll
                for (int j = 0; j < 8; j++) acc[i][j] += am[i] * bn[j];
        }
        __syncthreads();
    }

    // Epilogue: coalesced float4 stores along m
#pragma unroll
    for (int gj = 0; gj < 2; gj++)
#pragma unroll
        for (int j = 0; j < 4; j++) {
            int o = o0 + gj * 64 + ty * 4 + j;
            float bv = bias[o];
            float* dstrow = out + ((size_t)b * CDIM + o) * NTOK + m0;
#pragma unroll
            for (int gi = 0; gi < 2; gi++) {
                int ml = gi * 64 + tx * 4;
                float4 v4 = make_float4(acc[gi * 4 + 0][gj * 4 + j] + bv,
                                        acc[gi * 4 + 1][gj * 4 + j] + bv,
                                        acc[gi * 4 + 2][gj * 4 + j] + bv,
                                        acc[gi * 4 + 3][gj * 4 + j] + bv);
                *(float4*)&dstrow[ml] = v4;
            }
        }
}

// ---------------------------------------------------------------------------
extern "C" void kernel_launch(void* const* d_in, const int* in_sizes, int n_in,
                              void* d_out, int out_size) {
    const float* x     = (const float*)d_in[0];
    const float* Wqkv  = (const float*)d_in[1];
    const float* Wproj = (const float*)d_in[2];
    const float* bproj = (const float*)d_in[3];
    float* out = (float*)d_out;

    qkv_gemm<<<dim3(8, 9, 8), 256>>>(x, Wqkv);
    flash_attn<<<dim3(128, 12, 8), 256>>>();
    proj_gemm<<<dim3(8, 3, 8), 256>>>(Wproj, bproj, out);
}

// round 4
// speedup vs baseline: 1.8136x; 1.8136x over previous
#include <cuda_runtime.h>
#include <cstdint>

// Problem constants
#define BSZ   8
#define CDIM  384
#define NTOK  1024
#define NH    12
#define DH    32
static constexpr float SCALE = 0.17677669529663687f;  // 32^-0.5

typedef unsigned long long ull;

// Packed f32x2 helpers (Blackwell sm_103a: doubles fp32 FMA throughput vs 3-reg FFMA)
#define PACK2(d, lo, hi) \
    asm("mov.b64 %0, {%1, %2};" : "=l"(d) : "r"(__float_as_uint(lo)), "r"(__float_as_uint(hi)))
#define UNPACK2(lo, hi, s) \
    { unsigned _ulo, _uhi; \
      asm("mov.b64 {%0, %1}, %2;" : "=r"(_ulo), "=r"(_uhi) : "l"(s)); \
      lo = __uint_as_float(_ulo); hi = __uint_as_float(_uhi); }
#define FMA2(acc, a, b) \
    asm("fma.rn.f32x2 %0, %1, %2, %0;" : "+l"(acc) : "l"(a), "l"(b))
#define MUL2(acc, m) \
    asm("mul.rn.f32x2 %0, %0, %1;" : "+l"(acc) : "l"(m))

// Scratch (device globals; no allocations allowed)
static __device__ float g_q[(size_t)BSZ * NH * NTOK * DH];
static __device__ float g_k[(size_t)BSZ * NH * NTOK * DH];
static __device__ float g_v[(size_t)BSZ * NH * NTOK * DH];
static __device__ float g_o[(size_t)BSZ * NTOK * CDIM];

// ---------------------------------------------------------------------------
// Kernel 1: QKV projection.  out[b,m,o] = sum_c x[b,c,m] * Wqkv[o,c]
// 128x128 tile, BK=16, 256 threads. Inner product uses f32x2 (m-pairs packed).
// ---------------------------------------------------------------------------
__global__ __launch_bounds__(256) void qkv_gemm(const float* __restrict__ x,
                                                const float* __restrict__ W) {
    int b  = blockIdx.z;
    int m0 = blockIdx.x * 128;
    int o0 = blockIdx.y * 128;
    __shared__ float As[16][128];
    __shared__ float Bs[16][128];
    int t  = threadIdx.x;
    int tx = t & 15, ty = t >> 4;

    ull acc2[4][8];   // m-pairs {ty*4+0/1, ty*4+2/3, 64+ty*4+0/1, 64+ty*4+2/3} x 8 o
#pragma unroll
    for (int i = 0; i < 4; i++)
#pragma unroll
        for (int j = 0; j < 8; j++) acc2[i][j] = 0ull;

    const float* xb = x + (size_t)b * CDIM * NTOK;

    for (int k0 = 0; k0 < CDIM; k0 += 16) {
        {
            int kk = t >> 5;
            int m4 = (t & 31) * 4;
            const float* src = xb + (size_t)(k0 + kk) * NTOK + m0 + m4;
            *(float4*)&As[kk][m4]     = *(const float4*)src;
            *(float4*)&As[kk + 8][m4] = *(const float4*)(src + 8 * NTOK);
        }
        {
            int oo = t >> 1;
            int k8 = (t & 1) * 8;
            const float* ws = W + (size_t)(o0 + oo) * CDIM + k0 + k8;
            float4 w0 = *(const float4*)ws;
            float4 w1 = *(const float4*)(ws + 4);
            Bs[k8 + 0][oo] = w0.x; Bs[k8 + 1][oo] = w0.y;
            Bs[k8 + 2][oo] = w0.z; Bs[k8 + 3][oo] = w0.w;
            Bs[k8 + 4][oo] = w1.x; Bs[k8 + 5][oo] = w1.y;
            Bs[k8 + 6][oo] = w1.z; Bs[k8 + 7][oo] = w1.w;
        }
        __syncthreads();
#pragma unroll
        for (int kk = 0; kk < 16; kk++) {
            ulonglong2 a01 = *(const ulonglong2*)&As[kk][ty * 4];
            ulonglong2 a23 = *(const ulonglong2*)&As[kk][64 + ty * 4];
            ull a2[4] = {a01.x, a01.y, a23.x, a23.y};
            float4 b0 = *(const float4*)&Bs[kk][tx * 4];
            float4 b1 = *(const float4*)&Bs[kk][64 + tx * 4];
            ull b2[8];
            PACK2(b2[0], b0.x, b0.x); PACK2(b2[1], b0.y, b0.y);
            PACK2(b2[2], b0.z, b0.z); PACK2(b2[3], b0.w, b0.w);
            PACK2(b2[4], b1.x, b1.x); PACK2(b2[5], b1.y, b1.y);
            PACK2(b2[6], b1.z, b1.z); PACK2(b2[7], b1.w, b1.w);
#pragma unroll
            for (int i = 0; i < 4; i++)
#pragma unroll
                for (int j = 0; j < 8; j++) FMA2(acc2[i][j], a2[i], b2[j]);
        }
        __syncthreads();
    }

    // Epilogue: route o -> (s, h, d); unpack m-pairs.
#pragma unroll
    for (int i2 = 0; i2 < 4; i2++) {
        float rl[8], rh[8];
#pragma unroll
        for (int j = 0; j < 8; j++) UNPACK2(rl[j], rh[j], acc2[i2][j]);
#pragma unroll
        for (int half = 0; half < 2; half++) {
            int m = m0 + (i2 >> 1) * 64 + ty * 4 + (i2 & 1) * 2 + half;
            float* r = half ? rh : rl;
#pragma unroll
            for (int gj = 0; gj < 2; gj++) {
                int o   = o0 + gj * 64 + tx * 4;
                int s   = o / CDIM;
                int rem = o - s * CDIM;
                int h   = rem >> 5;
                int d   = rem & 31;
                float* dst = (s == 0) ? g_q : (s == 1) ? g_k : g_v;
                size_t idx = (((size_t)b * NH + h) * NTOK + m) * DH + d;
                *(float4*)&dst[idx] = make_float4(r[gj*4+0], r[gj*4+1],
                                                  r[gj*4+2], r[gj*4+3]);
            }
        }
    }
}

// ---------------------------------------------------------------------------
// Kernel 2: flash attention v2 — 2-GEMM register-tiled, online softmax.
// Q tile = 64, K chunk = 64, 256 threads (tx=k/d dim, ty=q dim).
// Thread: S tile 4q x 4k, O tile 4q x 2d. f32x2 with q-pairs packed.
// ---------------------------------------------------------------------------
__global__ __launch_bounds__(256) void flash_attn2() {
    __shared__ float Qs[32][68];   // [d][q], SCALE folded
    __shared__ float Ks[32][68];   // [d][k]
    __shared__ float Vs[64][36];   // [k][d]
    __shared__ float Ps[64][68];   // [k][q]

    int b    = blockIdx.z;
    int h    = blockIdx.y;
    int q0   = blockIdx.x * 64;
    int t    = threadIdx.x;
    int tx   = t & 15, ty = t >> 4;

    size_t base  = ((size_t)(b * NH + h) * NTOK) * DH;
    const float4* gq4 = (const float4*)(g_q + base);
    const float4* gk4 = (const float4*)(g_k + base);
    const float4* gv4 = (const float4*)(g_v + base);

    // Load Q tile transposed + scaled
#pragma unroll
    for (int i = 0; i < 2; i++) {
        int f4 = t + i * 256;           // 0..511
        int q  = f4 >> 3, d4 = f4 & 7;
        float4 v = gq4[q0 * 8 + f4];
        Qs[d4*4+0][q] = v.x * SCALE; Qs[d4*4+1][q] = v.y * SCALE;
        Qs[d4*4+2][q] = v.z * SCALE; Qs[d4*4+3][q] = v.w * SCALE;
    }

    float mr[4] = {-1e30f, -1e30f, -1e30f, -1e30f};
    float lr[4] = {0.f, 0.f, 0.f, 0.f};
    ull O2[2][2] = {{0ull, 0ull}, {0ull, 0ull}};   // q-pairs x d(tx*2, tx*2+1)

    for (int c = 0; c < 16; c++) {
        __syncthreads();   // (A) prior PV done reading Ks/Vs/Ps
#pragma unroll
        for (int i = 0; i < 2; i++) {
            int f4 = t + i * 256;
            int k  = f4 >> 3, d4 = f4 & 7;
            float4 kv = gk4[c * 512 + f4];
            Ks[d4*4+0][k] = kv.x; Ks[d4*4+1][k] = kv.y;
            Ks[d4*4+2][k] = kv.z; Ks[d4*4+3][k] = kv.w;
            *(float4*)&Vs[k][d4*4] = gv4[c * 512 + f4];
        }
        __syncthreads();   // (B)

        // ---- S GEMM: S[4q][4k] over d=32 ----
        ull S2[2][4] = {{0,0,0,0},{0,0,0,0}};
#pragma unroll
        for (int d = 0; d < 32; d++) {
            ulonglong2 a = *(const ulonglong2*)&Qs[d][ty * 4];
            float4 kv = *(const float4*)&Ks[d][tx * 4];
            ull b2[4];
            PACK2(b2[0], kv.x, kv.x); PACK2(b2[1], kv.y, kv.y);
            PACK2(b2[2], kv.z, kv.z); PACK2(b2[3], kv.w, kv.w);
#pragma unroll
            for (int j = 0; j < 4; j++) { FMA2(S2[0][j], a.x, b2[j]);
                                          FMA2(S2[1][j], a.y, b2[j]); }
        }

        // ---- online softmax ----
        float sl[2][4], sh[2][4];
#pragma unroll
        for (int i = 0; i < 2; i++)
#pragma unroll
            for (int j = 0; j < 4; j++) UNPACK2(sl[i][j], sh[i][j], S2[i][j]);

        float mc[4];
#pragma unroll
        for (int i = 0; i < 2; i++) {
            mc[2*i+0] = fmaxf(fmaxf(sl[i][0], sl[i][1]), fmaxf(sl[i][2], sl[i][3]));
            mc[2*i+1] = fmaxf(fmaxf(sh[i][0], sh[i][1]), fmaxf(sh[i][2], sh[i][3]));
        }
#pragma unroll
        for (int r = 0; r < 4; r++)
#pragma unroll
            for (int off = 8; off; off >>= 1)
                mc[r] = fmaxf(mc[r], __shfl_xor_sync(0xffffffffu, mc[r], off));

        float al[4];
#pragma unroll
        for (int r = 0; r < 4; r++) {
            float mn = fmaxf(mr[r], mc[r]);
            al[r] = __expf(mr[r] - mn);
            mr[r] = mn;
            lr[r] *= al[r];
        }
        ull al2[2];
        PACK2(al2[0], al[0], al[1]);
        PACK2(al2[1], al[2], al[3]);
#pragma unroll
        for (int i = 0; i < 2; i++) { MUL2(O2[i][0], al2[i]); MUL2(O2[i][1], al2[i]); }

#pragma unroll
        for (int i = 0; i < 2; i++)
#pragma unroll
            for (int j = 0; j < 4; j++) {
                float pl = __expf(sl[i][j] - mr[2*i+0]);
                float ph = __expf(sh[i][j] - mr[2*i+1]);
                lr[2*i+0] += pl; lr[2*i+1] += ph;
                sl[i][j] = pl; sh[i][j] = ph;
            }
#pragma unroll
        for (int j = 0; j < 4; j++)
            *(float4*)&Ps[tx*4+j][ty*4] =
                make_float4(sl[0][j], sh[0][j], sl[1][j], sh[1][j]);

        __syncthreads();   // (C) Ps visible

        // ---- PV GEMM: O[4q][2d] += P[4q][64k] * V[64k][2d] ----
#pragma unroll 4
        for (int k = 0; k < 64; k++) {
            ulonglong2 a = *(const ulonglong2*)&Ps[k][ty * 4];
            float2 vv = *(const float2*)&Vs[k][tx * 2];
            ull b0, b1;
            PACK2(b0, vv.x, vv.x); PACK2(b1, vv.y, vv.y);
            FMA2(O2[0][0], a.x, b0); FMA2(O2[0][1], a.x, b1);
            FMA2(O2[1][0], a.y, b0); FMA2(O2[1][1], a.y, b1);
        }
    }

    // final: reduce l across tx (each tx holds a disjoint 4-key slice per chunk)
#pragma unroll
    for (int r = 0; r < 4; r++)
#pragma unroll
        for (int off = 8; off; off >>= 1)
            lr[r] += __shfl_xor_sync(0xffffffffu, lr[r], off);

#pragma unroll
    for (int i = 0; i < 2; i++) {
        float o0l, o0h, o1l, o1h;
        UNPACK2(o0l, o0h, O2[i][0]);
        UNPACK2(o1l, o1h, O2[i][1]);
        float inv0 = 1.f / lr[2*i+0];
        float inv1 = 1.f / lr[2*i+1];
        int qa = q0 + ty * 4 + 2*i;
        float* dst0 = &g_o[((size_t)b * NTOK + qa)     * CDIM + h * DH + tx * 2];
        float* dst1 = &g_o[((size_t)b * NTOK + qa + 1) * CDIM + h * DH + tx * 2];
        *(float2*)dst0 = make_float2(o0l * inv0, o1l * inv0);
        *(float2*)dst1 = make_float2(o0h * inv1, o1h * inv1);
    }
}

// ---------------------------------------------------------------------------
// Kernel 3: output projection + bias, transposed store. f32x2 inner loop.
// ---------------------------------------------------------------------------
__global__ __launch_bounds__(256) void proj_gemm(const float* __restrict__ W,
                                                 const float* __restrict__ bias,
                                                 float* __restrict__ out) {
    int b  = blockIdx.z;
    int m0 = blockIdx.x * 128;
    int o0 = blockIdx.y * 128;
    __shared__ float As[16][128];
    __shared__ float Bs[16][128];
    int t  = threadIdx.x;
    int tx = t & 15, ty = t >> 4;

    ull acc2[4][8];   // m-pairs (tx dim) x 8 o (ty dim)
#pragma unroll
    for (int i = 0; i < 4; i++)
#pragma unroll
        for (int j = 0; j < 8; j++) acc2[i][j] = 0ull;

    const float* ao = g_o + (size_t)b * NTOK * CDIM;

    for (int k0 = 0; k0 < CDIM; k0 += 16) {
        {
            int mm = t >> 1;
            int k8 = (t & 1) * 8;
            const float* src = ao + (size_t)(m0 + mm) * CDIM + k0 + k8;
            float4 a0 = *(const float4*)src;
            float4 a1 = *(const float4*)(src + 4);
            As[k8 + 0][mm] = a0.x; As[k8 + 1][mm] = a0.y;
            As[k8 + 2][mm] = a0.z; As[k8 + 3][mm] = a0.w;
            As[k8 + 4][mm] = a1.x; As[k8 + 5][mm] = a1.y;
            As[k8 + 6][mm] = a1.z; As[k8 + 7][mm] = a1.w;

            const float* ws = W + (size_t)(o0 + mm) * CDIM + k0 + k8;
            float4 w0 = *(const float4*)ws;
            float4 w1 = *(const float4*)(ws + 4);
            Bs[k8 + 0][mm] = w0.x; Bs[k8 + 1][mm] = w0.y;
            Bs[k8 + 2][mm] = w0.z; Bs[k8 + 3][mm] = w0.w;
            Bs[k8 + 4][mm] = w1.x; Bs[k8 + 5][mm] = w1.y;
            Bs[k8 + 6][mm] = w1.z; Bs[k8 + 7][mm] = w1.w;
        }
        __syncthreads();
#pragma unroll
        for (int kk = 0; kk < 16; kk++) {
            ulonglong2 a01 = *(const ulonglong2*)&As[kk][tx * 4];
            ulonglong2 a23 = *(const ulonglong2*)&As[kk][64 + tx * 4];
            ull a2[4] = {a01.x, a01.y, a23.x, a23.y};
            float4 b0 = *(const float4*)&Bs[kk][ty * 4];
            float4 b1 = *(const float4*)&Bs[kk][64 + ty * 4];
            ull b2[8];
            PACK2(b2[0], b0.x, b0.x); PACK2(b2[1], b0.y, b0.y);
            PACK2(b2[2], b0.z, b0.z); PACK2(b2[3], b0.w, b0.w);
            PACK2(b2[4], b1.x, b1.x); PACK2(b2[5], b1.y, b1.y);
            PACK2(b2[6], b1.z, b1.z); PACK2(b2[7], b1.w, b1.w);
#pragma unroll
            for (int i = 0; i < 4; i++)
#pragma unroll
                for (int j = 0; j < 8; j++) FMA2(acc2[i][j], a2[i], b2[j]);
        }
        __syncthreads();
    }

    // Epilogue: coalesced float4 stores along m (m is the packed dim)
#pragma unroll
    for (int gj = 0; gj < 2; gj++)
#pragma unroll
        for (int j = 0; j < 4; j++) {
            int J = gj * 4 + j;
            int o = o0 + gj * 64 + ty * 4 + j;
            float bv = bias[o];
            float* dstrow = out + ((size_t)b * CDIM + o) * NTOK + m0;
#pragma unroll
            for (int gi = 0; gi < 2; gi++) {
                float v0l, v0h, v1l, v1h;
                UNPACK2(v0l, v0h, acc2[gi*2 + 0][J]);
                UNPACK2(v1l, v1h, acc2[gi*2 + 1][J]);
                int ml = gi * 64 + tx * 4;
                *(float4*)&dstrow[ml] = make_float4(v0l + bv, v0h + bv,
                                                    v1l + bv, v1h + bv);
            }
        }
}

// ---------------------------------------------------------------------------
extern "C" void kernel_launch(void* const* d_in, const int* in_sizes, int n_in,
                              void* d_out, int out_size) {
    const float* x     = (const float*)d_in[0];
    const float* Wqkv  = (const float*)d_in[1];
    const float* Wproj = (const float*)d_in[2];
    const float* bproj = (const float*)d_in[3];
    float* out = (float*)d_out;

    qkv_gemm<<<dim3(8, 9, 8), 256>>>(x, Wqkv);
    flash_attn2<<<dim3(16, 12, 8), 256>>>();
    proj_gemm<<<dim3(8, 3, 8), 256>>>(Wproj, bproj, out);
}